// round 5
// baseline (speedup 1.0000x reference)
#include <cuda_runtime.h>
#include <math.h>

// ---------------- problem-size maxima (this dataset: N=50000, E=800000) ----
#define NMAX 50000
#define EMAX 800000
#define ETMAX (EMAX + NMAX)

// ---------------- scratch (device globals; referenced directly by kernels) --
__device__ float g_h1[(size_t)NMAX * 256];    // layer1 linear output [N,256]
__device__ float g_h2in[(size_t)NMAX * 256];  // layer1 GAT output (+bias,relu)
__device__ float g_h2[(size_t)NMAX * 64];     // layer2 linear output [N,64]
__device__ float g_as1[(size_t)NMAX * 4];
__device__ float g_ad1[(size_t)NMAX * 4];
__device__ float g_as2[NMAX];
__device__ float g_ad2[NMAX];
__device__ int g_counts[NMAX];
__device__ int g_offsets[NMAX + 1];
__device__ int g_cursor[NMAX];
__device__ int g_srcs[ETMAX];
__device__ int g_is64;  // 1 if edge_index is int64, 0 if int32

// compile-time buffer selection (resolved at compile time inside kernels)
#define BUF_H1 0
#define BUF_H2IN 1
#define BUF_H2 2
#define BUF_AS1 3
#define BUF_AD1 4
#define BUF_AS2 5
#define BUF_AD2 6
__device__ __forceinline__ float* fbuf(int id) {
    switch (id) {
        case BUF_H1: return g_h1;
        case BUF_H2IN: return g_h2in;
        case BUF_H2: return g_h2;
        case BUF_AS1: return g_as1;
        case BUF_AD1: return g_ad1;
        case BUF_AS2: return g_as2;
        default: return g_ad2;
    }
}

// ---------------- edge_index dtype detection --------------------------------
// int64 nonneg values < 2^31 have zero high words; int32 data at those word
// positions is random edge IDs (essentially never all zero over 4096 samples).
__global__ void detect_dtype_kernel(const unsigned int* __restrict__ w) {
    __shared__ int any_nz;
    if (threadIdx.x == 0) any_nz = 0;
    __syncthreads();
    int nz = 0;
    for (int k = threadIdx.x; k < 4096; k += blockDim.x)
        if (w[2 * k + 1] != 0u) nz = 1;
    if (nz) atomicOr(&any_nz, 1);
    __syncthreads();
    if (threadIdx.x == 0) g_is64 = any_nz ? 0 : 1;
}

__device__ __forceinline__ int edge_val(const void* ei, long long idx) {
    if (g_is64) return (int)((const long long*)ei)[idx];
    return ((const int*)ei)[idx];
}

// ---------------- CSR build -------------------------------------------------
__global__ void init_counts_kernel(int N) {
    int i = blockIdx.x * blockDim.x + threadIdx.x;
    if (i < N) g_counts[i] = 1;  // self-loop pre-counted
}

__global__ void hist_kernel(const void* __restrict__ ei, int E, int N) {
    int i = blockIdx.x * blockDim.x + threadIdx.x;
    if (i < E) {
        int dst = edge_val(ei, (long long)E + i);
        if (dst >= 0 && dst < N) atomicAdd(&g_counts[dst], 1);
    }
}

// single-block exclusive scan over N elements; also seeds cursor
__global__ void scan_kernel(int N) {
    __shared__ int sh[1024];
    __shared__ int run;
    int t = threadIdx.x;
    if (t == 0) run = 0;
    __syncthreads();
    for (int base = 0; base < N; base += 1024) {
        int i = base + t;
        int v = (i < N) ? g_counts[i] : 0;
        sh[t] = v;
        __syncthreads();
        for (int o = 1; o < 1024; o <<= 1) {
            int tmp = (t >= o) ? sh[t - o] : 0;
            __syncthreads();
            sh[t] += tmp;
            __syncthreads();
        }
        if (i < N) {
            int excl = run + sh[t] - v;  // exclusive prefix
            g_offsets[i] = excl;
            g_cursor[i] = excl;
        }
        __syncthreads();
        if (t == 1023) run += sh[1023];
        __syncthreads();
    }
    if (t == 0) g_offsets[N] = run;
}

__global__ void scatter_kernel(const void* __restrict__ ei, int E, int N) {
    int i = blockIdx.x * blockDim.x + threadIdx.x;
    int src, dst;
    if (i < E) {
        src = edge_val(ei, i);
        dst = edge_val(ei, (long long)E + i);
    } else if (i < E + N) {
        src = dst = i - E;  // self loop
    } else {
        return;
    }
    if (src < 0 || src >= N || dst < 0 || dst >= N) return;
    int pos = atomicAdd(&g_cursor[dst], 1);
    if (pos >= 0 && pos < ETMAX) g_srcs[pos] = src;
}

// ---------------- fp32 tiled GEMM: C[M,N] = A[M,K] @ B[K,N] (row-major) -----
// ASEL/CSEL: -1 -> use param pointer, else fbuf(id)
template <int BM, int BN, int BK, int TM, int TN, int ASEL, int CSEL>
__global__ void sgemm_kernel(const float* __restrict__ Ap, const float* __restrict__ B,
                             float* __restrict__ Cp, int M, int N, int K) {
    const float* A = (ASEL < 0) ? Ap : fbuf(ASEL);
    float* C = (CSEL < 0) ? Cp : fbuf(CSEL);
    __shared__ float As[BK][BM];
    __shared__ float Bs[BK][BN];
    constexpr int TX = BN / TN;
    const int tx = threadIdx.x % TX;
    const int ty = threadIdx.x / TX;
    const int row0 = blockIdx.y * BM;
    const int col0 = blockIdx.x * BN;

    float acc[TM][TN];
#pragma unroll
    for (int i = 0; i < TM; i++)
#pragma unroll
        for (int j = 0; j < TN; j++) acc[i][j] = 0.f;

    for (int k0 = 0; k0 < K; k0 += BK) {
#pragma unroll
        for (int i = threadIdx.x; i < BM * BK / 4; i += 256) {
            int r = i / (BK / 4);
            int c = 4 * (i % (BK / 4));
            float4 v = make_float4(0.f, 0.f, 0.f, 0.f);
            if (row0 + r < M)
                v = *reinterpret_cast<const float4*>(&A[(size_t)(row0 + r) * K + k0 + c]);
            As[c + 0][r] = v.x;
            As[c + 1][r] = v.y;
            As[c + 2][r] = v.z;
            As[c + 3][r] = v.w;
        }
#pragma unroll
        for (int i = threadIdx.x; i < BK * BN; i += 256) {
            int r = i / BN, c = i % BN;
            Bs[r][c] = B[(size_t)(k0 + r) * N + col0 + c];
        }
        __syncthreads();
#pragma unroll
        for (int kk = 0; kk < BK; kk++) {
            float a[TM], b[TN];
#pragma unroll
            for (int i = 0; i < TM; i++) a[i] = As[kk][ty * TM + i];
#pragma unroll
            for (int j = 0; j < TN; j++) b[j] = Bs[kk][tx * TN + j];
#pragma unroll
            for (int i = 0; i < TM; i++)
#pragma unroll
                for (int j = 0; j < TN; j++) acc[i][j] = fmaf(a[i], b[j], acc[i][j]);
        }
        __syncthreads();
    }
#pragma unroll
    for (int i = 0; i < TM; i++) {
        int r = row0 + ty * TM + i;
        if (r < M) {
#pragma unroll
            for (int j = 0; j < TN; j++)
                C[(size_t)r * N + col0 + tx * TN + j] = acc[i][j];
        }
    }
}

// ---------------- per-node attention coefficients ---------------------------
template <int H, int C, int HSEL, int ASSEL, int ADSEL>
__global__ void alpha_kernel(const float* __restrict__ a_src,
                             const float* __restrict__ a_dst, int N) {
    const float* h = fbuf(HSEL);
    float* as_out = fbuf(ASSEL);
    float* ad_out = fbuf(ADSEL);
    constexpr int HC = H * C, J = HC / 32;
    int w = blockIdx.x * (blockDim.x >> 5) + (threadIdx.x >> 5);
    int lane = threadIdx.x & 31;
    if (w >= N) return;
    float ps[H], pd[H];
#pragma unroll
    for (int hh = 0; hh < H; hh++) { ps[hh] = 0.f; pd[hh] = 0.f; }
#pragma unroll
    for (int j = 0; j < J; j++) {
        int f = lane + 32 * j;
        int hh = f / C;
        float v = h[(size_t)w * HC + f];
        ps[hh] = fmaf(v, a_src[f], ps[hh]);
        pd[hh] = fmaf(v, a_dst[f], pd[hh]);
    }
#pragma unroll
    for (int hh = 0; hh < H; hh++) {
#pragma unroll
        for (int o = 16; o > 0; o >>= 1) {
            ps[hh] += __shfl_xor_sync(0xffffffffu, ps[hh], o);
            pd[hh] += __shfl_xor_sync(0xffffffffu, pd[hh], o);
        }
    }
    if (lane == 0) {
#pragma unroll
        for (int hh = 0; hh < H; hh++) {
            as_out[(size_t)w * H + hh] = ps[hh];
            ad_out[(size_t)w * H + hh] = pd[hh];
        }
    }
}

__device__ __forceinline__ float lrelu(float x) { return x > 0.f ? x : 0.2f * x; }

// ---------------- GAT aggregation: one warp per dst node --------------------
// OSEL: -1 -> write param pointer (d_out), else fbuf(id)
template <int H, int C, int HSEL, int ASSEL, int ADSEL, int OSEL, int DO_RELU>
__global__ void aggregate_kernel(const float* __restrict__ bias, float* __restrict__ outp,
                                 int N) {
    const float* h = fbuf(HSEL);
    const float* as = fbuf(ASSEL);
    const float* ad = fbuf(ADSEL);
    float* out = (OSEL < 0) ? outp : fbuf(OSEL);
    constexpr int HC = H * C, J = HC / 32;
    int w = blockIdx.x * (blockDim.x >> 5) + (threadIdx.x >> 5);
    int lane = threadIdx.x & 31;
    if (w >= N) return;
    const int beg = g_offsets[w], end = g_offsets[w + 1];

    float adv[H];
#pragma unroll
    for (int hh = 0; hh < H; hh++) adv[hh] = ad[(size_t)w * H + hh];

    // pass 1a: segment max per head
    float m[H];
#pragma unroll
    for (int hh = 0; hh < H; hh++) m[hh] = -1e30f;
    for (int e = beg + lane; e < end; e += 32) {
        int s = g_srcs[e];
#pragma unroll
        for (int hh = 0; hh < H; hh++) {
            float ev = lrelu(as[(size_t)s * H + hh] + adv[hh]);
            m[hh] = fmaxf(m[hh], ev);
        }
    }
#pragma unroll
    for (int hh = 0; hh < H; hh++)
#pragma unroll
        for (int o = 16; o > 0; o >>= 1)
            m[hh] = fmaxf(m[hh], __shfl_xor_sync(0xffffffffu, m[hh], o));

    // pass 1b: segment sum of exp
    float sum[H];
#pragma unroll
    for (int hh = 0; hh < H; hh++) sum[hh] = 0.f;
    for (int e = beg + lane; e < end; e += 32) {
        int s = g_srcs[e];
#pragma unroll
        for (int hh = 0; hh < H; hh++) {
            float ev = lrelu(as[(size_t)s * H + hh] + adv[hh]);
            sum[hh] += __expf(ev - m[hh]);
        }
    }
#pragma unroll
    for (int hh = 0; hh < H; hh++)
#pragma unroll
        for (int o = 16; o > 0; o >>= 1)
            sum[hh] += __shfl_xor_sync(0xffffffffu, sum[hh], o);

    float inv[H];
#pragma unroll
    for (int hh = 0; hh < H; hh++) inv[hh] = 1.0f / (sum[hh] + 1e-16f);

    // pass 2: weighted feature gather-accumulate
    float acc[J];
#pragma unroll
    for (int j = 0; j < J; j++) acc[j] = 0.f;
    for (int e = beg; e < end; e++) {
        int s = g_srcs[e];
        float wv[H];
#pragma unroll
        for (int hh = 0; hh < H; hh++) {
            float ev = lrelu(as[(size_t)s * H + hh] + adv[hh]);
            wv[hh] = __expf(ev - m[hh]) * inv[hh];
        }
        const float* hrow = h + (size_t)s * HC;
#pragma unroll
        for (int j = 0; j < J; j++) {
            int f = lane + 32 * j;
            acc[j] = fmaf(wv[f / C], hrow[f], acc[j]);
        }
    }
#pragma unroll
    for (int j = 0; j < J; j++) {
        int f = lane + 32 * j;
        float v = acc[j] + bias[f];
        if (DO_RELU) v = fmaxf(v, 0.f);
        out[(size_t)w * HC + f] = v;
    }
}

// ---------------- launcher: kernel launches ONLY -----------------------------
extern "C" void kernel_launch(void* const* d_in, const int* in_sizes, int n_in,
                              void* d_out, int out_size) {
    const float* x = (const float*)d_in[0];     // [N,128]
    const void* ei = d_in[1];                   // [2,E] int64 or int32
    const float* W1 = (const float*)d_in[2];    // [128,256]
    const float* a_s1 = (const float*)d_in[3];  // [4,64]
    const float* a_d1 = (const float*)d_in[4];  // [4,64]
    const float* b1 = (const float*)d_in[5];    // [256]
    const float* W2 = (const float*)d_in[6];    // [256,64]
    const float* a_s2 = (const float*)d_in[7];  // [1,64]
    const float* a_d2 = (const float*)d_in[8];  // [1,64]
    const float* b2 = (const float*)d_in[9];    // [64]
    float* out = (float*)d_out;                 // [N,64]

    const int N = in_sizes[0] / 128;
    const int E = in_sizes[1] / 2;

    // CSR by dst (self loops included)
    detect_dtype_kernel<<<1, 256>>>((const unsigned int*)ei);
    init_counts_kernel<<<(N + 255) / 256, 256>>>(N);
    hist_kernel<<<(E + 255) / 256, 256>>>(ei, E, N);
    scan_kernel<<<1, 1024>>>(N);
    scatter_kernel<<<(E + N + 255) / 256, 256>>>(ei, E, N);

    const int warp_blocks = (N + 7) / 8;  // 8 warps per 256-thread block

    // Layer 1: h1 = x@W1 ; alphas ; aggregate(+bias,relu) -> h2in
    sgemm_kernel<128, 64, 16, 8, 4, -1, BUF_H1>
        <<<dim3(256 / 64, (N + 127) / 128), 256>>>(x, W1, nullptr, N, 256, 128);
    alpha_kernel<4, 64, BUF_H1, BUF_AS1, BUF_AD1><<<warp_blocks, 256>>>(a_s1, a_d1, N);
    aggregate_kernel<4, 64, BUF_H1, BUF_AS1, BUF_AD1, BUF_H2IN, 1>
        <<<warp_blocks, 256>>>(b1, nullptr, N);

    // Layer 2: h2 = h2in@W2 ; alphas ; aggregate(+bias) -> out
    sgemm_kernel<128, 64, 16, 8, 4, BUF_H2IN, BUF_H2>
        <<<dim3(64 / 64, (N + 127) / 128), 256>>>(nullptr, W2, nullptr, N, 64, 256);
    alpha_kernel<1, 64, BUF_H2, BUF_AS2, BUF_AD2><<<warp_blocks, 256>>>(a_s2, a_d2, N);
    aggregate_kernel<1, 64, BUF_H2, BUF_AS2, BUF_AD2, -1, 0>
        <<<warp_blocks, 256>>>(b2, out, N);
}

// round 6
// speedup vs baseline: 1.0437x; 1.0437x over previous
#include <cuda_runtime.h>
#include <math.h>

// ---------------- problem-size maxima (this dataset: N=50000, E=800000) ----
#define NMAX 50000
#define EMAX 800000
#define ETMAX (EMAX + NMAX)

// ---------------- scratch (device globals; referenced directly by kernels) --
__device__ float g_h1[(size_t)NMAX * 256];    // layer1 linear output [N,256]
__device__ float g_h2in[(size_t)NMAX * 256];  // layer1 GAT output (+bias,relu)
__device__ float g_h2[(size_t)NMAX * 64];     // layer2 linear output [N,64]
__device__ float g_as1[(size_t)NMAX * 4];
__device__ float g_ad1[(size_t)NMAX * 4];
__device__ float g_as2[NMAX];
__device__ float g_ad2[NMAX];
__device__ int g_counts[NMAX];
__device__ int g_offsets[NMAX + 1];
__device__ int g_cursor[NMAX];
__device__ int g_srcs[ETMAX];
__device__ int g_is64;  // 1 if edge_index is int64, 0 if int32

// compile-time buffer selection (resolved at compile time inside kernels)
#define BUF_H1 0
#define BUF_H2IN 1
#define BUF_H2 2
#define BUF_AS1 3
#define BUF_AD1 4
#define BUF_AS2 5
#define BUF_AD2 6
__device__ __forceinline__ float* fbuf(int id) {
    switch (id) {
        case BUF_H1: return g_h1;
        case BUF_H2IN: return g_h2in;
        case BUF_H2: return g_h2;
        case BUF_AS1: return g_as1;
        case BUF_AD1: return g_ad1;
        case BUF_AS2: return g_as2;
        default: return g_ad2;
    }
}

// ---------------- edge_index dtype detection --------------------------------
__global__ void detect_dtype_kernel(const unsigned int* __restrict__ w) {
    __shared__ int any_nz;
    if (threadIdx.x == 0) any_nz = 0;
    __syncthreads();
    int nz = 0;
    for (int k = threadIdx.x; k < 4096; k += blockDim.x)
        if (w[2 * k + 1] != 0u) nz = 1;
    if (nz) atomicOr(&any_nz, 1);
    __syncthreads();
    if (threadIdx.x == 0) g_is64 = any_nz ? 0 : 1;
}

__device__ __forceinline__ int edge_val(const void* ei, long long idx) {
    if (g_is64) return (int)((const long long*)ei)[idx];
    return ((const int*)ei)[idx];
}

// ---------------- CSR build -------------------------------------------------
__global__ void init_counts_kernel(int N) {
    int i = blockIdx.x * blockDim.x + threadIdx.x;
    if (i < N) g_counts[i] = 1;  // self-loop pre-counted
}

__global__ void hist_kernel(const void* __restrict__ ei, int E, int N) {
    int i = blockIdx.x * blockDim.x + threadIdx.x;
    if (i < E) {
        int dst = edge_val(ei, (long long)E + i);
        if (dst >= 0 && dst < N) atomicAdd(&g_counts[dst], 1);
    }
}

// thread-coarsened warp-shuffle exclusive scan; single block, 1024 threads.
// Each thread owns a contiguous chunk; 2 barriers total.
__global__ void scan_kernel(int N) {
    const int t = threadIdx.x;
    const int PER = (N + 1023) >> 10;
    const int start = t * PER;

    int sum = 0;
    for (int k = 0; k < PER; k++) {
        int i = start + k;
        if (i < N) sum += g_counts[i];
    }

    // inclusive warp scan of per-thread sums
    const int lane = t & 31, wid = t >> 5;
    int v = sum;
#pragma unroll
    for (int o = 1; o < 32; o <<= 1) {
        int u = __shfl_up_sync(0xffffffffu, v, o);
        if (lane >= o) v += u;
    }
    __shared__ int wsum[32];
    if (lane == 31) wsum[wid] = v;
    __syncthreads();
    if (wid == 0) {
        int w = wsum[lane];
#pragma unroll
        for (int o = 1; o < 32; o <<= 1) {
            int u = __shfl_up_sync(0xffffffffu, w, o);
            if (lane >= o) w += u;
        }
        wsum[lane] = w;
    }
    __syncthreads();

    int run = v - sum + (wid > 0 ? wsum[wid - 1] : 0);  // exclusive prefix of chunk
    for (int k = 0; k < PER; k++) {
        int i = start + k;
        if (i < N) {
            int c = g_counts[i];
            g_offsets[i] = run;
            g_cursor[i] = run;
            run += c;
        }
    }
    if (t == 1023) g_offsets[N] = run;  // total (tail-safe: skipped adds keep run=total)
}

__global__ void scatter_kernel(const void* __restrict__ ei, int E, int N) {
    int i = blockIdx.x * blockDim.x + threadIdx.x;
    int src, dst;
    if (i < E) {
        src = edge_val(ei, i);
        dst = edge_val(ei, (long long)E + i);
    } else if (i < E + N) {
        src = dst = i - E;  // self loop
    } else {
        return;
    }
    if (src < 0 || src >= N || dst < 0 || dst >= N) return;
    int pos = atomicAdd(&g_cursor[dst], 1);
    if (pos >= 0 && pos < ETMAX) g_srcs[pos] = src;
}

// ---------------- fp32 tiled GEMM: C[M,N] = A[M,K] @ B[K,N] (row-major) -----
// ASEL/CSEL: -1 -> use param pointer, else fbuf(id)
template <int BM, int BN, int BK, int TM, int TN, int ASEL, int CSEL>
__global__ void sgemm_kernel(const float* __restrict__ Ap, const float* __restrict__ B,
                             float* __restrict__ Cp, int M, int N, int K) {
    const float* A = (ASEL < 0) ? Ap : fbuf(ASEL);
    float* C = (CSEL < 0) ? Cp : fbuf(CSEL);
    __shared__ float As[BK][BM];
    __shared__ float Bs[BK][BN];
    constexpr int TX = BN / TN;
    const int tx = threadIdx.x % TX;
    const int ty = threadIdx.x / TX;
    const int row0 = blockIdx.y * BM;
    const int col0 = blockIdx.x * BN;

    float acc[TM][TN];
#pragma unroll
    for (int i = 0; i < TM; i++)
#pragma unroll
        for (int j = 0; j < TN; j++) acc[i][j] = 0.f;

    for (int k0 = 0; k0 < K; k0 += BK) {
        // A tile: float4 along K, store transposed
#pragma unroll
        for (int i = threadIdx.x; i < BM * BK / 4; i += 256) {
            int r = i / (BK / 4);
            int c = 4 * (i % (BK / 4));
            float4 v = make_float4(0.f, 0.f, 0.f, 0.f);
            if (row0 + r < M)
                v = *reinterpret_cast<const float4*>(&A[(size_t)(row0 + r) * K + k0 + c]);
            As[c + 0][r] = v.x;
            As[c + 1][r] = v.y;
            As[c + 2][r] = v.z;
            As[c + 3][r] = v.w;
        }
        // B tile: float4 along N
#pragma unroll
        for (int i = threadIdx.x; i < BK * BN / 4; i += 256) {
            int r = i / (BN / 4);
            int c = 4 * (i % (BN / 4));
            float4 v = *reinterpret_cast<const float4*>(&B[(size_t)(k0 + r) * N + col0 + c]);
            *reinterpret_cast<float4*>(&Bs[r][c]) = v;
        }
        __syncthreads();
#pragma unroll
        for (int kk = 0; kk < BK; kk++) {
            float a[TM], b[TN];
#pragma unroll
            for (int i = 0; i < TM; i++) a[i] = As[kk][ty * TM + i];
#pragma unroll
            for (int j = 0; j < TN; j++) b[j] = Bs[kk][tx * TN + j];
#pragma unroll
            for (int i = 0; i < TM; i++)
#pragma unroll
                for (int j = 0; j < TN; j++) acc[i][j] = fmaf(a[i], b[j], acc[i][j]);
        }
        __syncthreads();
    }
#pragma unroll
    for (int i = 0; i < TM; i++) {
        int r = row0 + ty * TM + i;
        if (r < M) {
#pragma unroll
            for (int j = 0; j < TN; j++)
                C[(size_t)r * N + col0 + tx * TN + j] = acc[i][j];
        }
    }
}

// ---------------- per-node attention coefficients ---------------------------
template <int H, int C, int HSEL, int ASSEL, int ADSEL>
__global__ void alpha_kernel(const float* __restrict__ a_src,
                             const float* __restrict__ a_dst, int N) {
    const float* h = fbuf(HSEL);
    float* as_out = fbuf(ASSEL);
    float* ad_out = fbuf(ADSEL);
    constexpr int HC = H * C, J = HC / 32;
    int w = blockIdx.x * (blockDim.x >> 5) + (threadIdx.x >> 5);
    int lane = threadIdx.x & 31;
    if (w >= N) return;
    float ps[H], pd[H];
#pragma unroll
    for (int hh = 0; hh < H; hh++) { ps[hh] = 0.f; pd[hh] = 0.f; }
#pragma unroll
    for (int j = 0; j < J; j++) {
        int f = lane + 32 * j;
        int hh = f / C;
        float v = h[(size_t)w * HC + f];
        ps[hh] = fmaf(v, a_src[f], ps[hh]);
        pd[hh] = fmaf(v, a_dst[f], pd[hh]);
    }
#pragma unroll
    for (int hh = 0; hh < H; hh++) {
#pragma unroll
        for (int o = 16; o > 0; o >>= 1) {
            ps[hh] += __shfl_xor_sync(0xffffffffu, ps[hh], o);
            pd[hh] += __shfl_xor_sync(0xffffffffu, pd[hh], o);
        }
    }
    if (lane == 0) {
#pragma unroll
        for (int hh = 0; hh < H; hh++) {
            as_out[(size_t)w * H + hh] = ps[hh];
            ad_out[(size_t)w * H + hh] = pd[hh];
        }
    }
}

__device__ __forceinline__ float lrelu(float x) { return x > 0.f ? x : 0.2f * x; }

// ---------------- GAT aggregation: one warp per dst node --------------------
template <int H, int C, int HSEL, int ASSEL, int ADSEL, int OSEL, int DO_RELU>
__global__ void aggregate_kernel(const float* __restrict__ bias, float* __restrict__ outp,
                                 int N) {
    const float* h = fbuf(HSEL);
    const float* as = fbuf(ASSEL);
    const float* ad = fbuf(ADSEL);
    float* out = (OSEL < 0) ? outp : fbuf(OSEL);
    constexpr int HC = H * C, J = HC / 32;
    int w = blockIdx.x * (blockDim.x >> 5) + (threadIdx.x >> 5);
    int lane = threadIdx.x & 31;
    if (w >= N) return;
    const int beg = g_offsets[w], end = g_offsets[w + 1];

    float adv[H];
#pragma unroll
    for (int hh = 0; hh < H; hh++) adv[hh] = ad[(size_t)w * H + hh];

    // pass 1a: segment max per head
    float m[H];
#pragma unroll
    for (int hh = 0; hh < H; hh++) m[hh] = -1e30f;
    for (int e = beg + lane; e < end; e += 32) {
        int s = g_srcs[e];
#pragma unroll
        for (int hh = 0; hh < H; hh++) {
            float ev = lrelu(as[(size_t)s * H + hh] + adv[hh]);
            m[hh] = fmaxf(m[hh], ev);
        }
    }
#pragma unroll
    for (int hh = 0; hh < H; hh++)
#pragma unroll
        for (int o = 16; o > 0; o >>= 1)
            m[hh] = fmaxf(m[hh], __shfl_xor_sync(0xffffffffu, m[hh], o));

    // pass 1b: segment sum of exp
    float sum[H];
#pragma unroll
    for (int hh = 0; hh < H; hh++) sum[hh] = 0.f;
    for (int e = beg + lane; e < end; e += 32) {
        int s = g_srcs[e];
#pragma unroll
        for (int hh = 0; hh < H; hh++) {
            float ev = lrelu(as[(size_t)s * H + hh] + adv[hh]);
            sum[hh] += __expf(ev - m[hh]);
        }
    }
#pragma unroll
    for (int hh = 0; hh < H; hh++)
#pragma unroll
        for (int o = 16; o > 0; o >>= 1)
            sum[hh] += __shfl_xor_sync(0xffffffffu, sum[hh], o);

    float inv[H];
#pragma unroll
    for (int hh = 0; hh < H; hh++) inv[hh] = 1.0f / (sum[hh] + 1e-16f);

    // pass 2: weighted feature gather-accumulate
    float acc[J];
#pragma unroll
    for (int j = 0; j < J; j++) acc[j] = 0.f;
    for (int e = beg; e < end; e++) {
        int s = g_srcs[e];
        float wv[H];
#pragma unroll
        for (int hh = 0; hh < H; hh++) {
            float ev = lrelu(as[(size_t)s * H + hh] + adv[hh]);
            wv[hh] = __expf(ev - m[hh]) * inv[hh];
        }
        const float* hrow = h + (size_t)s * HC;
#pragma unroll
        for (int j = 0; j < J; j++) {
            int f = lane + 32 * j;
            acc[j] = fmaf(wv[f / C], hrow[f], acc[j]);
        }
    }
#pragma unroll
    for (int j = 0; j < J; j++) {
        int f = lane + 32 * j;
        float v = acc[j] + bias[f];
        if (DO_RELU) v = fmaxf(v, 0.f);
        out[(size_t)w * HC + f] = v;
    }
}

// ---------------- launcher: kernel launches ONLY -----------------------------
extern "C" void kernel_launch(void* const* d_in, const int* in_sizes, int n_in,
                              void* d_out, int out_size) {
    const float* x = (const float*)d_in[0];     // [N,128]
    const void* ei = d_in[1];                   // [2,E] int64 or int32
    const float* W1 = (const float*)d_in[2];    // [128,256]
    const float* a_s1 = (const float*)d_in[3];  // [4,64]
    const float* a_d1 = (const float*)d_in[4];  // [4,64]
    const float* b1 = (const float*)d_in[5];    // [256]
    const float* W2 = (const float*)d_in[6];    // [256,64]
    const float* a_s2 = (const float*)d_in[7];  // [1,64]
    const float* a_d2 = (const float*)d_in[8];  // [1,64]
    const float* b2 = (const float*)d_in[9];    // [64]
    float* out = (float*)d_out;                 // [N,64]

    const int N = in_sizes[0] / 128;
    const int E = in_sizes[1] / 2;

    // CSR by dst (self loops included)
    detect_dtype_kernel<<<1, 256>>>((const unsigned int*)ei);
    init_counts_kernel<<<(N + 255) / 256, 256>>>(N);
    hist_kernel<<<(E + 255) / 256, 256>>>(ei, E, N);
    scan_kernel<<<1, 1024>>>(N);
    scatter_kernel<<<(E + N + 255) / 256, 256>>>(ei, E, N);

    const int warp_blocks = (N + 7) / 8;  // 8 warps per 256-thread block

    // Layer 1: h1 = x@W1 ; alphas ; aggregate(+bias,relu) -> h2in
    sgemm_kernel<128, 64, 32, 8, 4, -1, BUF_H1>
        <<<dim3(256 / 64, (N + 127) / 128), 256>>>(x, W1, nullptr, N, 256, 128);
    alpha_kernel<4, 64, BUF_H1, BUF_AS1, BUF_AD1><<<warp_blocks, 256>>>(a_s1, a_d1, N);
    aggregate_kernel<4, 64, BUF_H1, BUF_AS1, BUF_AD1, BUF_H2IN, 1>
        <<<warp_blocks, 256>>>(b1, nullptr, N);

    // Layer 2: h2 = h2in@W2 ; alphas ; aggregate(+bias) -> out
    sgemm_kernel<128, 64, 32, 8, 4, BUF_H2IN, BUF_H2>
        <<<dim3(64 / 64, (N + 127) / 128), 256>>>(nullptr, W2, nullptr, N, 64, 256);
    alpha_kernel<1, 64, BUF_H2, BUF_AS2, BUF_AD2><<<warp_blocks, 256>>>(a_s2, a_d2, N);
    aggregate_kernel<1, 64, BUF_H2, BUF_AS2, BUF_AD2, -1, 0>
        <<<warp_blocks, 256>>>(b2, out, N);
}

// round 7
// speedup vs baseline: 1.2608x; 1.2080x over previous
#include <cuda_runtime.h>
#include <math.h>

// ---------------- problem-size maxima (this dataset: N=50000, E=800000) ----
#define NMAX 50000
#define EMAX 800000
#define ETMAX (EMAX + NMAX)
#define SCAN_NB ((NMAX + 1023) / 1024)

// ---------------- scratch (device globals; referenced directly by kernels) --
__device__ float g_h1[(size_t)NMAX * 256];    // layer1 linear output [N,256]
__device__ float g_h2in[(size_t)NMAX * 256];  // layer1 GAT output (+bias,relu)
__device__ float g_h2[(size_t)NMAX * 64];     // layer2 linear output [N,64]
__device__ float g_as1[(size_t)NMAX * 4];
__device__ float g_ad1[(size_t)NMAX * 4];
__device__ float g_as2[NMAX];
__device__ float g_ad2[NMAX];
__device__ int g_counts[NMAX];
__device__ int g_offsets[NMAX + 1];
__device__ int g_cursor[NMAX];
__device__ int g_srcs[ETMAX];
__device__ int g_blocksums[SCAN_NB];
__device__ int g_blockoffs[SCAN_NB];
__device__ int g_is64;  // 1 if edge_index is int64, 0 if int32

// compile-time buffer selection (resolved at compile time inside kernels)
#define BUF_H1 0
#define BUF_H2IN 1
#define BUF_H2 2
#define BUF_AS1 3
#define BUF_AD1 4
#define BUF_AS2 5
#define BUF_AD2 6
__device__ __forceinline__ float* fbuf(int id) {
    switch (id) {
        case BUF_H1: return g_h1;
        case BUF_H2IN: return g_h2in;
        case BUF_H2: return g_h2;
        case BUF_AS1: return g_as1;
        case BUF_AD1: return g_ad1;
        case BUF_AS2: return g_as2;
        default: return g_ad2;
    }
}

// ---------------- edge_index dtype detection --------------------------------
__global__ void detect_dtype_kernel(const unsigned int* __restrict__ w) {
    __shared__ int any_nz;
    if (threadIdx.x == 0) any_nz = 0;
    __syncthreads();
    int nz = 0;
    for (int k = threadIdx.x; k < 4096; k += blockDim.x)
        if (w[2 * k + 1] != 0u) nz = 1;
    if (nz) atomicOr(&any_nz, 1);
    __syncthreads();
    if (threadIdx.x == 0) g_is64 = any_nz ? 0 : 1;
}

__device__ __forceinline__ int edge_val(const void* ei, long long idx) {
    if (g_is64) return (int)((const long long*)ei)[idx];
    return ((const int*)ei)[idx];
}

// ---------------- CSR build -------------------------------------------------
__global__ void init_counts_kernel(int N) {
    int i = blockIdx.x * blockDim.x + threadIdx.x;
    if (i < N) g_counts[i] = 1;  // self-loop pre-counted
}

__global__ void hist_kernel(const void* __restrict__ ei, int E, int N) {
    int i = blockIdx.x * blockDim.x + threadIdx.x;
    if (i < E) {
        int dst = edge_val(ei, (long long)E + i);
        if (dst >= 0 && dst < N) atomicAdd(&g_counts[dst], 1);
    }
}

// in-block inclusive scan of v over 1024 threads; returns inclusive value;
// *total gets block sum. 2 barriers.
__device__ __forceinline__ int block_incl_scan(int v, int* total) {
    const int lane = threadIdx.x & 31, wid = threadIdx.x >> 5;
    int incl = v;
#pragma unroll
    for (int o = 1; o < 32; o <<= 1) {
        int u = __shfl_up_sync(0xffffffffu, incl, o);
        if (lane >= o) incl += u;
    }
    __shared__ int wsum[32];
    if (lane == 31) wsum[wid] = incl;
    __syncthreads();
    if (wid == 0) {
        int w = wsum[lane];
#pragma unroll
        for (int o = 1; o < 32; o <<= 1) {
            int u = __shfl_up_sync(0xffffffffu, w, o);
            if (lane >= o) w += u;
        }
        wsum[lane] = w;
    }
    __syncthreads();
    if (wid > 0) incl += wsum[wid - 1];
    *total = wsum[31];
    return incl;
}

// phase 1: per-block exclusive scan (coalesced), emit block sums
__global__ void scan_phase1(int N) {
    int i = blockIdx.x * 1024 + threadIdx.x;
    int v = (i < N) ? g_counts[i] : 0;
    int total;
    int incl = block_incl_scan(v, &total);
    if (i < N) g_offsets[i] = incl - v;  // block-local exclusive
    if (threadIdx.x == 1023) g_blocksums[blockIdx.x] = total;
}

// phase 2: scan of block sums (nb <= 1024); also writes grand total
__global__ void scan_phase2(int nb, int N) {
    int t = threadIdx.x;
    int v = (t < nb) ? g_blocksums[t] : 0;
    int total;
    int incl = block_incl_scan(v, &total);
    if (t < nb) g_blockoffs[t] = incl - v;
    if (t == 0) g_offsets[N] = total;
}

// phase 3: add block prefix; seed cursor
__global__ void scan_phase3(int N) {
    int i = blockIdx.x * 1024 + threadIdx.x;
    if (i < N) {
        int v = g_offsets[i] + g_blockoffs[blockIdx.x];
        g_offsets[i] = v;
        g_cursor[i] = v;
    }
}

__global__ void scatter_kernel(const void* __restrict__ ei, int E, int N) {
    int i = blockIdx.x * blockDim.x + threadIdx.x;
    int src, dst;
    if (i < E) {
        src = edge_val(ei, i);
        dst = edge_val(ei, (long long)E + i);
    } else if (i < E + N) {
        src = dst = i - E;  // self loop
    } else {
        return;
    }
    if (src < 0 || src >= N || dst < 0 || dst >= N) return;
    int pos = atomicAdd(&g_cursor[dst], 1);
    if (pos >= 0 && pos < ETMAX) g_srcs[pos] = src;
}

// ---------------- fp32 tiled GEMM: C[M,N] = A[M,K] @ B[K,N] (row-major) -----
template <int BM, int BN, int BK, int TM, int TN, int ASEL, int CSEL>
__global__ void sgemm_kernel(const float* __restrict__ Ap, const float* __restrict__ B,
                             float* __restrict__ Cp, int M, int N, int K) {
    const float* A = (ASEL < 0) ? Ap : fbuf(ASEL);
    float* C = (CSEL < 0) ? Cp : fbuf(CSEL);
    __shared__ float As[BK][BM];
    __shared__ float Bs[BK][BN];
    constexpr int TX = BN / TN;
    const int tx = threadIdx.x % TX;
    const int ty = threadIdx.x / TX;
    const int row0 = blockIdx.y * BM;
    const int col0 = blockIdx.x * BN;

    float acc[TM][TN];
#pragma unroll
    for (int i = 0; i < TM; i++)
#pragma unroll
        for (int j = 0; j < TN; j++) acc[i][j] = 0.f;

    for (int k0 = 0; k0 < K; k0 += BK) {
#pragma unroll
        for (int i = threadIdx.x; i < BM * BK / 4; i += 256) {
            int r = i / (BK / 4);
            int c = 4 * (i % (BK / 4));
            float4 v = make_float4(0.f, 0.f, 0.f, 0.f);
            if (row0 + r < M)
                v = *reinterpret_cast<const float4*>(&A[(size_t)(row0 + r) * K + k0 + c]);
            As[c + 0][r] = v.x;
            As[c + 1][r] = v.y;
            As[c + 2][r] = v.z;
            As[c + 3][r] = v.w;
        }
#pragma unroll
        for (int i = threadIdx.x; i < BK * BN / 4; i += 256) {
            int r = i / (BN / 4);
            int c = 4 * (i % (BN / 4));
            float4 v = *reinterpret_cast<const float4*>(&B[(size_t)(k0 + r) * N + col0 + c]);
            *reinterpret_cast<float4*>(&Bs[r][c]) = v;
        }
        __syncthreads();
#pragma unroll
        for (int kk = 0; kk < BK; kk++) {
            float a[TM], b[TN];
#pragma unroll
            for (int i = 0; i < TM; i++) a[i] = As[kk][ty * TM + i];
#pragma unroll
            for (int j = 0; j < TN; j++) b[j] = Bs[kk][tx * TN + j];
#pragma unroll
            for (int i = 0; i < TM; i++)
#pragma unroll
                for (int j = 0; j < TN; j++) acc[i][j] = fmaf(a[i], b[j], acc[i][j]);
        }
        __syncthreads();
    }
#pragma unroll
    for (int i = 0; i < TM; i++) {
        int r = row0 + ty * TM + i;
        if (r < M) {
#pragma unroll
            for (int j = 0; j < TN; j++)
                C[(size_t)r * N + col0 + tx * TN + j] = acc[i][j];
        }
    }
}

// ---------------- per-node attention coefficients ---------------------------
template <int H, int C, int HSEL, int ASSEL, int ADSEL>
__global__ void alpha_kernel(const float* __restrict__ a_src,
                             const float* __restrict__ a_dst, int N) {
    const float* h = fbuf(HSEL);
    float* as_out = fbuf(ASSEL);
    float* ad_out = fbuf(ADSEL);
    constexpr int HC = H * C, J = HC / 32;
    int w = blockIdx.x * (blockDim.x >> 5) + (threadIdx.x >> 5);
    int lane = threadIdx.x & 31;
    if (w >= N) return;
    float ps[H], pd[H];
#pragma unroll
    for (int hh = 0; hh < H; hh++) { ps[hh] = 0.f; pd[hh] = 0.f; }
#pragma unroll
    for (int j = 0; j < J; j++) {
        int f = lane + 32 * j;
        int hh = f / C;
        float v = h[(size_t)w * HC + f];
        ps[hh] = fmaf(v, a_src[f], ps[hh]);
        pd[hh] = fmaf(v, a_dst[f], pd[hh]);
    }
#pragma unroll
    for (int hh = 0; hh < H; hh++) {
#pragma unroll
        for (int o = 16; o > 0; o >>= 1) {
            ps[hh] += __shfl_xor_sync(0xffffffffu, ps[hh], o);
            pd[hh] += __shfl_xor_sync(0xffffffffu, pd[hh], o);
        }
    }
    if (lane == 0) {
#pragma unroll
        for (int hh = 0; hh < H; hh++) {
            as_out[(size_t)w * H + hh] = ps[hh];
            ad_out[(size_t)w * H + hh] = pd[hh];
        }
    }
}

__device__ __forceinline__ float lrelu(float x) { return x > 0.f ? x : 0.2f * x; }

// ---------------- GAT aggregation: one warp per dst node --------------------
template <int H, int C, int HSEL, int ASSEL, int ADSEL, int OSEL, int DO_RELU>
__global__ void aggregate_kernel(const float* __restrict__ bias, float* __restrict__ outp,
                                 int N) {
    const float* h = fbuf(HSEL);
    const float* as = fbuf(ASSEL);
    const float* ad = fbuf(ADSEL);
    float* out = (OSEL < 0) ? outp : fbuf(OSEL);
    constexpr int HC = H * C, J = HC / 32;
    int w = blockIdx.x * (blockDim.x >> 5) + (threadIdx.x >> 5);
    int lane = threadIdx.x & 31;
    if (w >= N) return;
    const int beg = g_offsets[w], end = g_offsets[w + 1];

    float adv[H];
#pragma unroll
    for (int hh = 0; hh < H; hh++) adv[hh] = ad[(size_t)w * H + hh];

    float m[H];
#pragma unroll
    for (int hh = 0; hh < H; hh++) m[hh] = -1e30f;
    for (int e = beg + lane; e < end; e += 32) {
        int s = g_srcs[e];
#pragma unroll
        for (int hh = 0; hh < H; hh++) {
            float ev = lrelu(as[(size_t)s * H + hh] + adv[hh]);
            m[hh] = fmaxf(m[hh], ev);
        }
    }
#pragma unroll
    for (int hh = 0; hh < H; hh++)
#pragma unroll
        for (int o = 16; o > 0; o >>= 1)
            m[hh] = fmaxf(m[hh], __shfl_xor_sync(0xffffffffu, m[hh], o));

    float sum[H];
#pragma unroll
    for (int hh = 0; hh < H; hh++) sum[hh] = 0.f;
    for (int e = beg + lane; e < end; e += 32) {
        int s = g_srcs[e];
#pragma unroll
        for (int hh = 0; hh < H; hh++) {
            float ev = lrelu(as[(size_t)s * H + hh] + adv[hh]);
            sum[hh] += __expf(ev - m[hh]);
        }
    }
#pragma unroll
    for (int hh = 0; hh < H; hh++)
#pragma unroll
        for (int o = 16; o > 0; o >>= 1)
            sum[hh] += __shfl_xor_sync(0xffffffffu, sum[hh], o);

    float inv[H];
#pragma unroll
    for (int hh = 0; hh < H; hh++) inv[hh] = 1.0f / (sum[hh] + 1e-16f);

    float acc[J];
#pragma unroll
    for (int j = 0; j < J; j++) acc[j] = 0.f;
    for (int e = beg; e < end; e++) {
        int s = g_srcs[e];
        float wv[H];
#pragma unroll
        for (int hh = 0; hh < H; hh++) {
            float ev = lrelu(as[(size_t)s * H + hh] + adv[hh]);
            wv[hh] = __expf(ev - m[hh]) * inv[hh];
        }
        const float* hrow = h + (size_t)s * HC;
#pragma unroll
        for (int j = 0; j < J; j++) {
            int f = lane + 32 * j;
            acc[j] = fmaf(wv[f / C], hrow[f], acc[j]);
        }
    }
#pragma unroll
    for (int j = 0; j < J; j++) {
        int f = lane + 32 * j;
        float v = acc[j] + bias[f];
        if (DO_RELU) v = fmaxf(v, 0.f);
        out[(size_t)w * HC + f] = v;
    }
}

// ---------------- launcher: kernel launches ONLY -----------------------------
extern "C" void kernel_launch(void* const* d_in, const int* in_sizes, int n_in,
                              void* d_out, int out_size) {
    const float* x = (const float*)d_in[0];     // [N,128]
    const void* ei = d_in[1];                   // [2,E] int64 or int32
    const float* W1 = (const float*)d_in[2];    // [128,256]
    const float* a_s1 = (const float*)d_in[3];  // [4,64]
    const float* a_d1 = (const float*)d_in[4];  // [4,64]
    const float* b1 = (const float*)d_in[5];    // [256]
    const float* W2 = (const float*)d_in[6];    // [256,64]
    const float* a_s2 = (const float*)d_in[7];  // [1,64]
    const float* a_d2 = (const float*)d_in[8];  // [1,64]
    const float* b2 = (const float*)d_in[9];    // [64]
    float* out = (float*)d_out;                 // [N,64]

    const int N = in_sizes[0] / 128;
    const int E = in_sizes[1] / 2;
    const int nb = (N + 1023) / 1024;

    // CSR by dst (self loops included)
    detect_dtype_kernel<<<1, 256>>>((const unsigned int*)ei);
    init_counts_kernel<<<(N + 255) / 256, 256>>>(N);
    hist_kernel<<<(E + 255) / 256, 256>>>(ei, E, N);
    scan_phase1<<<nb, 1024>>>(N);
    scan_phase2<<<1, 1024>>>(nb, N);
    scan_phase3<<<nb, 1024>>>(N);
    scatter_kernel<<<(E + N + 255) / 256, 256>>>(ei, E, N);

    const int warp_blocks = (N + 7) / 8;  // 8 warps per 256-thread block

    // Layer 1: h1 = x@W1 ; alphas ; aggregate(+bias,relu) -> h2in
    sgemm_kernel<128, 64, 32, 8, 4, -1, BUF_H1>
        <<<dim3(256 / 64, (N + 127) / 128), 256>>>(x, W1, nullptr, N, 256, 128);
    alpha_kernel<4, 64, BUF_H1, BUF_AS1, BUF_AD1><<<warp_blocks, 256>>>(a_s1, a_d1, N);
    aggregate_kernel<4, 64, BUF_H1, BUF_AS1, BUF_AD1, BUF_H2IN, 1>
        <<<warp_blocks, 256>>>(b1, nullptr, N);

    // Layer 2: h2 = h2in@W2 ; alphas ; aggregate(+bias) -> out
    sgemm_kernel<128, 64, 32, 8, 4, BUF_H2IN, BUF_H2>
        <<<dim3(64 / 64, (N + 127) / 128), 256>>>(nullptr, W2, nullptr, N, 64, 256);
    alpha_kernel<1, 64, BUF_H2, BUF_AS2, BUF_AD2><<<warp_blocks, 256>>>(a_s2, a_d2, N);
    aggregate_kernel<1, 64, BUF_H2, BUF_AS2, BUF_AD2, -1, 0>
        <<<warp_blocks, 256>>>(b2, out, N);
}

// round 8
// speedup vs baseline: 1.2615x; 1.0006x over previous
#include <cuda_runtime.h>
#include <math.h>

// ---------------- problem-size maxima (this dataset: N=50000, E=800000) ----
#define NMAX 50000
#define EMAX 800000
#define ETMAX (EMAX + NMAX)
#define SCAN_NB ((NMAX + 1023) / 1024)

// ---------------- scratch (device globals; referenced directly by kernels) --
__device__ float g_h1[(size_t)NMAX * 256];    // layer1 linear output [N,256]
__device__ float g_h2in[(size_t)NMAX * 256];  // layer1 GAT output (+bias,relu)
__device__ float g_h2[(size_t)NMAX * 64];     // layer2 linear output [N,64]
__device__ float g_as1[(size_t)NMAX * 4];
__device__ float g_ad1[(size_t)NMAX * 4];
__device__ float g_as2[NMAX];
__device__ float g_ad2[NMAX];
__device__ int g_counts[NMAX];
__device__ int g_offsets[NMAX + 1];
__device__ int g_cursor[NMAX];
__device__ int g_srcs[ETMAX];
__device__ int g_blocksums[SCAN_NB];
__device__ int g_blockoffs[SCAN_NB];
__device__ int g_is64;  // 1 if edge_index is int64, 0 if int32

// compile-time buffer selection (resolved at compile time inside kernels)
#define BUF_H1 0
#define BUF_H2IN 1
#define BUF_H2 2
#define BUF_AS1 3
#define BUF_AD1 4
#define BUF_AS2 5
#define BUF_AD2 6
__device__ __forceinline__ float* fbuf(int id) {
    switch (id) {
        case BUF_H1: return g_h1;
        case BUF_H2IN: return g_h2in;
        case BUF_H2: return g_h2;
        case BUF_AS1: return g_as1;
        case BUF_AD1: return g_ad1;
        case BUF_AS2: return g_as2;
        default: return g_ad2;
    }
}

// ---------------- edge_index dtype detection --------------------------------
__global__ void detect_dtype_kernel(const unsigned int* __restrict__ w) {
    __shared__ int any_nz;
    if (threadIdx.x == 0) any_nz = 0;
    __syncthreads();
    int nz = 0;
    for (int k = threadIdx.x; k < 4096; k += blockDim.x)
        if (w[2 * k + 1] != 0u) nz = 1;
    if (nz) atomicOr(&any_nz, 1);
    __syncthreads();
    if (threadIdx.x == 0) g_is64 = any_nz ? 0 : 1;
}

__device__ __forceinline__ int edge_val(const void* ei, long long idx) {
    if (g_is64) return (int)((const long long*)ei)[idx];
    return ((const int*)ei)[idx];
}

// ---------------- CSR build -------------------------------------------------
__global__ void init_counts_kernel(int N) {
    int i = blockIdx.x * blockDim.x + threadIdx.x;
    if (i < N) g_counts[i] = 1;  // self-loop pre-counted
}

__global__ void hist_kernel(const void* __restrict__ ei, int E, int N) {
    int i = blockIdx.x * blockDim.x + threadIdx.x;
    if (i < E) {
        int dst = edge_val(ei, (long long)E + i);
        if (dst >= 0 && dst < N) atomicAdd(&g_counts[dst], 1);
    }
}

// in-block inclusive scan of v over 1024 threads; returns inclusive value;
// *total gets block sum. 2 barriers.
__device__ __forceinline__ int block_incl_scan(int v, int* total) {
    const int lane = threadIdx.x & 31, wid = threadIdx.x >> 5;
    int incl = v;
#pragma unroll
    for (int o = 1; o < 32; o <<= 1) {
        int u = __shfl_up_sync(0xffffffffu, incl, o);
        if (lane >= o) incl += u;
    }
    __shared__ int wsum[32];
    if (lane == 31) wsum[wid] = incl;
    __syncthreads();
    if (wid == 0) {
        int w = wsum[lane];
#pragma unroll
        for (int o = 1; o < 32; o <<= 1) {
            int u = __shfl_up_sync(0xffffffffu, w, o);
            if (lane >= o) w += u;
        }
        wsum[lane] = w;
    }
    __syncthreads();
    if (wid > 0) incl += wsum[wid - 1];
    *total = wsum[31];
    return incl;
}

// phase 1: per-block exclusive scan (coalesced), emit block sums
__global__ void scan_phase1(int N) {
    int i = blockIdx.x * 1024 + threadIdx.x;
    int v = (i < N) ? g_counts[i] : 0;
    int total;
    int incl = block_incl_scan(v, &total);
    if (i < N) g_offsets[i] = incl - v;  // block-local exclusive
    if (threadIdx.x == 1023) g_blocksums[blockIdx.x] = total;
}

// phase 2: scan of block sums (nb <= 1024); also writes grand total
__global__ void scan_phase2(int nb, int N) {
    int t = threadIdx.x;
    int v = (t < nb) ? g_blocksums[t] : 0;
    int total;
    int incl = block_incl_scan(v, &total);
    if (t < nb) g_blockoffs[t] = incl - v;
    if (t == 0) g_offsets[N] = total;
}

// phase 3: add block prefix; seed cursor
__global__ void scan_phase3(int N) {
    int i = blockIdx.x * 1024 + threadIdx.x;
    if (i < N) {
        int v = g_offsets[i] + g_blockoffs[blockIdx.x];
        g_offsets[i] = v;
        g_cursor[i] = v;
    }
}

__global__ void scatter_kernel(const void* __restrict__ ei, int E, int N) {
    int i = blockIdx.x * blockDim.x + threadIdx.x;
    int src, dst;
    if (i < E) {
        src = edge_val(ei, i);
        dst = edge_val(ei, (long long)E + i);
    } else if (i < E + N) {
        src = dst = i - E;  // self loop
    } else {
        return;
    }
    if (src < 0 || src >= N || dst < 0 || dst >= N) return;
    int pos = atomicAdd(&g_cursor[dst], 1);
    if (pos >= 0 && pos < ETMAX) g_srcs[pos] = src;
}

// ---------------- fp32 tiled GEMM: C[M,N] = A[M,K] @ B[K,N] (row-major) -----
template <int BM, int BN, int BK, int TM, int TN, int ASEL, int CSEL>
__global__ void sgemm_kernel(const float* __restrict__ Ap, const float* __restrict__ B,
                             float* __restrict__ Cp, int M, int N, int K) {
    const float* A = (ASEL < 0) ? Ap : fbuf(ASEL);
    float* C = (CSEL < 0) ? Cp : fbuf(CSEL);
    __shared__ float As[BK][BM];
    __shared__ float Bs[BK][BN];
    constexpr int TX = BN / TN;
    const int tx = threadIdx.x % TX;
    const int ty = threadIdx.x / TX;
    const int row0 = blockIdx.y * BM;
    const int col0 = blockIdx.x * BN;

    float acc[TM][TN];
#pragma unroll
    for (int i = 0; i < TM; i++)
#pragma unroll
        for (int j = 0; j < TN; j++) acc[i][j] = 0.f;

    for (int k0 = 0; k0 < K; k0 += BK) {
#pragma unroll
        for (int i = threadIdx.x; i < BM * BK / 4; i += 256) {
            int r = i / (BK / 4);
            int c = 4 * (i % (BK / 4));
            float4 v = make_float4(0.f, 0.f, 0.f, 0.f);
            if (row0 + r < M)
                v = *reinterpret_cast<const float4*>(&A[(size_t)(row0 + r) * K + k0 + c]);
            As[c + 0][r] = v.x;
            As[c + 1][r] = v.y;
            As[c + 2][r] = v.z;
            As[c + 3][r] = v.w;
        }
#pragma unroll
        for (int i = threadIdx.x; i < BK * BN / 4; i += 256) {
            int r = i / (BN / 4);
            int c = 4 * (i % (BN / 4));
            float4 v = *reinterpret_cast<const float4*>(&B[(size_t)(k0 + r) * N + col0 + c]);
            *reinterpret_cast<float4*>(&Bs[r][c]) = v;
        }
        __syncthreads();
#pragma unroll
        for (int kk = 0; kk < BK; kk++) {
            float a[TM], b[TN];
#pragma unroll
            for (int i = 0; i < TM; i++) a[i] = As[kk][ty * TM + i];
#pragma unroll
            for (int j = 0; j < TN; j++) b[j] = Bs[kk][tx * TN + j];
#pragma unroll
            for (int i = 0; i < TM; i++)
#pragma unroll
                for (int j = 0; j < TN; j++) acc[i][j] = fmaf(a[i], b[j], acc[i][j]);
        }
        __syncthreads();
    }
#pragma unroll
    for (int i = 0; i < TM; i++) {
        int r = row0 + ty * TM + i;
        if (r < M) {
#pragma unroll
            for (int j = 0; j < TN; j++)
                C[(size_t)r * N + col0 + tx * TN + j] = acc[i][j];
        }
    }
}

// ---------------- per-node attention coefficients ---------------------------
template <int H, int C, int HSEL, int ASSEL, int ADSEL>
__global__ void alpha_kernel(const float* __restrict__ a_src,
                             const float* __restrict__ a_dst, int N) {
    const float* h = fbuf(HSEL);
    float* as_out = fbuf(ASSEL);
    float* ad_out = fbuf(ADSEL);
    constexpr int HC = H * C, J = HC / 32;
    int w = blockIdx.x * (blockDim.x >> 5) + (threadIdx.x >> 5);
    int lane = threadIdx.x & 31;
    if (w >= N) return;
    float ps[H], pd[H];
#pragma unroll
    for (int hh = 0; hh < H; hh++) { ps[hh] = 0.f; pd[hh] = 0.f; }
#pragma unroll
    for (int j = 0; j < J; j++) {
        int f = lane + 32 * j;
        int hh = f / C;
        float v = h[(size_t)w * HC + f];
        ps[hh] = fmaf(v, a_src[f], ps[hh]);
        pd[hh] = fmaf(v, a_dst[f], pd[hh]);
    }
#pragma unroll
    for (int hh = 0; hh < H; hh++) {
#pragma unroll
        for (int o = 16; o > 0; o >>= 1) {
            ps[hh] += __shfl_xor_sync(0xffffffffu, ps[hh], o);
            pd[hh] += __shfl_xor_sync(0xffffffffu, pd[hh], o);
        }
    }
    if (lane == 0) {
#pragma unroll
        for (int hh = 0; hh < H; hh++) {
            as_out[(size_t)w * H + hh] = ps[hh];
            ad_out[(size_t)w * H + hh] = pd[hh];
        }
    }
}

__device__ __forceinline__ float lrelu(float x) { return x > 0.f ? x : 0.2f * x; }

// ---------------- GAT aggregation: one warp per dst node --------------------
template <int H, int C, int HSEL, int ASSEL, int ADSEL, int OSEL, int DO_RELU>
__global__ void aggregate_kernel(const float* __restrict__ bias, float* __restrict__ outp,
                                 int N) {
    const float* h = fbuf(HSEL);
    const float* as = fbuf(ASSEL);
    const float* ad = fbuf(ADSEL);
    float* out = (OSEL < 0) ? outp : fbuf(OSEL);
    constexpr int HC = H * C, J = HC / 32;
    int w = blockIdx.x * (blockDim.x >> 5) + (threadIdx.x >> 5);
    int lane = threadIdx.x & 31;
    if (w >= N) return;
    const int beg = g_offsets[w], end = g_offsets[w + 1];

    float adv[H];
#pragma unroll
    for (int hh = 0; hh < H; hh++) adv[hh] = ad[(size_t)w * H + hh];

    float m[H];
#pragma unroll
    for (int hh = 0; hh < H; hh++) m[hh] = -1e30f;
    for (int e = beg + lane; e < end; e += 32) {
        int s = g_srcs[e];
#pragma unroll
        for (int hh = 0; hh < H; hh++) {
            float ev = lrelu(as[(size_t)s * H + hh] + adv[hh]);
            m[hh] = fmaxf(m[hh], ev);
        }
    }
#pragma unroll
    for (int hh = 0; hh < H; hh++)
#pragma unroll
        for (int o = 16; o > 0; o >>= 1)
            m[hh] = fmaxf(m[hh], __shfl_xor_sync(0xffffffffu, m[hh], o));

    float sum[H];
#pragma unroll
    for (int hh = 0; hh < H; hh++) sum[hh] = 0.f;
    for (int e = beg + lane; e < end; e += 32) {
        int s = g_srcs[e];
#pragma unroll
        for (int hh = 0; hh < H; hh++) {
            float ev = lrelu(as[(size_t)s * H + hh] + adv[hh]);
            sum[hh] += __expf(ev - m[hh]);
        }
    }
#pragma unroll
    for (int hh = 0; hh < H; hh++)
#pragma unroll
        for (int o = 16; o > 0; o >>= 1)
            sum[hh] += __shfl_xor_sync(0xffffffffu, sum[hh], o);

    float inv[H];
#pragma unroll
    for (int hh = 0; hh < H; hh++) inv[hh] = 1.0f / (sum[hh] + 1e-16f);

    float acc[J];
#pragma unroll
    for (int j = 0; j < J; j++) acc[j] = 0.f;
    for (int e = beg; e < end; e++) {
        int s = g_srcs[e];
        float wv[H];
#pragma unroll
        for (int hh = 0; hh < H; hh++) {
            float ev = lrelu(as[(size_t)s * H + hh] + adv[hh]);
            wv[hh] = __expf(ev - m[hh]) * inv[hh];
        }
        const float* hrow = h + (size_t)s * HC;
#pragma unroll
        for (int j = 0; j < J; j++) {
            int f = lane + 32 * j;
            acc[j] = fmaf(wv[f / C], hrow[f], acc[j]);
        }
    }
#pragma unroll
    for (int j = 0; j < J; j++) {
        int f = lane + 32 * j;
        float v = acc[j] + bias[f];
        if (DO_RELU) v = fmaxf(v, 0.f);
        out[(size_t)w * HC + f] = v;
    }
}

// ---------------- launcher: kernel launches ONLY -----------------------------
extern "C" void kernel_launch(void* const* d_in, const int* in_sizes, int n_in,
                              void* d_out, int out_size) {
    const float* x = (const float*)d_in[0];     // [N,128]
    const void* ei = d_in[1];                   // [2,E] int64 or int32
    const float* W1 = (const float*)d_in[2];    // [128,256]
    const float* a_s1 = (const float*)d_in[3];  // [4,64]
    const float* a_d1 = (const float*)d_in[4];  // [4,64]
    const float* b1 = (const float*)d_in[5];    // [256]
    const float* W2 = (const float*)d_in[6];    // [256,64]
    const float* a_s2 = (const float*)d_in[7];  // [1,64]
    const float* a_d2 = (const float*)d_in[8];  // [1,64]
    const float* b2 = (const float*)d_in[9];    // [64]
    float* out = (float*)d_out;                 // [N,64]

    const int N = in_sizes[0] / 128;
    const int E = in_sizes[1] / 2;
    const int nb = (N + 1023) / 1024;

    // CSR by dst (self loops included)
    detect_dtype_kernel<<<1, 256>>>((const unsigned int*)ei);
    init_counts_kernel<<<(N + 255) / 256, 256>>>(N);
    hist_kernel<<<(E + 255) / 256, 256>>>(ei, E, N);
    scan_phase1<<<nb, 1024>>>(N);
    scan_phase2<<<1, 1024>>>(nb, N);
    scan_phase3<<<nb, 1024>>>(N);
    scatter_kernel<<<(E + N + 255) / 256, 256>>>(ei, E, N);

    const int warp_blocks = (N + 7) / 8;  // 8 warps per 256-thread block

    // Layer 1: h1 = x@W1 ; alphas ; aggregate(+bias,relu) -> h2in
    sgemm_kernel<128, 64, 32, 8, 4, -1, BUF_H1>
        <<<dim3(256 / 64, (N + 127) / 128), 256>>>(x, W1, nullptr, N, 256, 128);
    alpha_kernel<4, 64, BUF_H1, BUF_AS1, BUF_AD1><<<warp_blocks, 256>>>(a_s1, a_d1, N);
    aggregate_kernel<4, 64, BUF_H1, BUF_AS1, BUF_AD1, BUF_H2IN, 1>
        <<<warp_blocks, 256>>>(b1, nullptr, N);

    // Layer 2: h2 = h2in@W2 ; alphas ; aggregate(+bias) -> out
    sgemm_kernel<128, 64, 32, 8, 4, BUF_H2IN, BUF_H2>
        <<<dim3(64 / 64, (N + 127) / 128), 256>>>(nullptr, W2, nullptr, N, 64, 256);
    alpha_kernel<1, 64, BUF_H2, BUF_AS2, BUF_AD2><<<warp_blocks, 256>>>(a_s2, a_d2, N);
    aggregate_kernel<1, 64, BUF_H2, BUF_AS2, BUF_AD2, -1, 0>
        <<<warp_blocks, 256>>>(b2, out, N);
}